// round 14
// baseline (speedup 1.0000x reference)
#include <cuda_runtime.h>
#include <cuda_bf16.h>

// Problem constants
#define B_SZ   512
#define IN_F   512
#define OUT_F  64
#define KD     16
#define NF     (OUT_F * KD)   // 1024

typedef unsigned long long u64;
typedef unsigned int u32;

// Scratch: bf16 inputs (x row-major, T transposed), bf16 M [o][b][k/2], S, counters
__device__ u32 g_xb[B_SZ * IN_F / 2];          // x as bf16x2, [m][k]
__device__ u32 g_Tb[NF * IN_F / 2];            // T^T as bf16x2, [n][k]
__device__ u32 g_Mb[OUT_F * B_SZ * KD / 2];    // M as bf16x2, [o][b][k/2]
__device__ float g_S[OUT_F * B_SZ];
__device__ unsigned int g_cnt[OUT_F * 4];      // zero-init, self-resetting

// ---- packed helpers (sm_103a) ---------------------------------------------
__device__ __forceinline__ u32 hadd2b(u32 a, u32 b) {
    u32 r; asm("add.rn.bf16x2 %0, %1, %2;" : "=r"(r) : "r"(a), "r"(b)); return r;
}
__device__ __forceinline__ u32 habs2(u32 a) { return a & 0x7FFF7FFFu; }
// pack two f32 into bf16x2: lo -> low half, hi -> high half
__device__ __forceinline__ u32 cvt2(float lo, float hi) {
    u32 r; asm("cvt.rn.bf16x2.f32 %0, %1, %2;" : "=r"(r) : "f"(hi), "f"(lo)); return r;
}
__device__ __forceinline__ void mma_bf16(float& d0, float& d1, float& d2, float& d3,
                                         u32 a0, u32 a1, u32 a2, u32 a3,
                                         u32 b0, u32 b1) {
    asm volatile(
        "mma.sync.aligned.m16n8k16.row.col.f32.bf16.bf16.f32 "
        "{%0,%1,%2,%3}, {%4,%5,%6,%7}, {%8,%9}, {%0,%1,%2,%3};"
        : "+f"(d0), "+f"(d1), "+f"(d2), "+f"(d3)
        : "r"(a0), "r"(a1), "r"(a2), "r"(a3), "r"(b0), "r"(b1));
}

// ---------------------------------------------------------------------------
// Kernel P: prep, reworked for latency hiding. Grid (16 n-tiles, 16 k-tiles)
// = 256 blocks x 256 threads (~14 warps/SM).
//  - x -> g_xb: one float4 (=2 bf16x2) per thread
//  - T tile 32k x 64n -> transposed bf16x2 g_Tb[n][k] via smem
//  - zeroes g_S (128 floats per block)
// ---------------------------------------------------------------------------
__global__ __launch_bounds__(256) void mbd_prep_kernel(
    const float* __restrict__ x, const float* __restrict__ T)
{
    __shared__ float sT[32][68];               // padded rows

    const int tid = threadIdx.x;
    const int bx  = blockIdx.x;                // 0..15  (n tile, 64 wide)
    const int by  = blockIdx.y;                // 0..15  (k tile, 32 tall)
    const int bid = by * 16 + bx;              // 0..255
    const int k0  = by * 32;
    const int n0  = bx * 64;

    // x conversion: 65536 float4 total -> 256 per block -> 1 per thread
    {
        int e = bid * 256 + tid;               // float4 index
        float4 f = ((const float4*)x)[e];
        g_xb[e * 2 + 0] = cvt2(f.x, f.y);
        g_xb[e * 2 + 1] = cvt2(f.z, f.w);
    }
    // g_S zeroing: 32768 floats -> 128 per block
    if (tid < 128)
        g_S[bid * 128 + tid] = 0.0f;

    // Load T tile (32 k-rows x 64 n-cols): 512 float4, 2 per thread
    {
#pragma unroll
        for (int t = 0; t < 2; t++) {
            int idx = tid + t * 256;
            int r = idx >> 4;                  // 0..31
            int c = idx & 15;                  // float4 col
            float4 v = ((const float4*)T)[(k0 + r) * (NF / 4) + (n0 / 4) + c];
            *(float4*)&sT[r][c * 4] = v;
        }
    }
    __syncthreads();

    // Write transposed bf16x2: g_Tb[n][k/2], 1024 u32, 4 per thread
    {
        int nn = tid >> 2;                     // 0..63
        int kb = tid & 3;
#pragma unroll
        for (int i = 0; i < 4; i++) {
            int ki = kb * 4 + i;               // u32 index within tile, 0..15
            u32 v = cvt2(sT[ki * 2][nn], sT[ki * 2 + 1][nn]);
            g_Tb[(n0 + nn) * (IN_F / 2) + k0 / 2 + ki] = v;
        }
    }
}

// ---------------------------------------------------------------------------
// Kernel A: bf16 tensor-core GEMM (UNCHANGED from R13).
// ---------------------------------------------------------------------------
#define GSTEP 8
#define RB 144

__global__ __launch_bounds__(128) void mbd_gemm_kernel(void)
{
    __shared__ unsigned char Asb[2][64 * RB];
    __shared__ unsigned char Bsb[2][64 * RB];

    const int tid = threadIdx.x;
    const int w   = tid >> 5;
    const int l   = tid & 31;
    const int g   = l >> 2;
    const int tg  = l & 3;
    const int nt  = blockIdx.x;
    const int mt  = blockIdx.y;
    const int m0  = mt * 64;
    const int n0  = nt * 64;

    const int sr = tid >> 1;
    const int sc = (tid & 1) * 4;
    const uint4* xs4 = (const uint4*)g_xb;
    const uint4* Ts4 = (const uint4*)g_Tb;

    float d[8][4];
#pragma unroll
    for (int nc = 0; nc < 8; nc++)
#pragma unroll
        for (int i = 0; i < 4; i++) d[nc][i] = 0.f;

#pragma unroll
    for (int i = 0; i < 4; i++) {
        uint4 va = xs4[(m0 + sr) * 64 + (sc + i)];
        uint4 vb = Ts4[(n0 + sr) * 64 + (sc + i)];
        *(uint4*)(Asb[0] + sr * RB + (sc + i) * 16) = va;
        *(uint4*)(Bsb[0] + sr * RB + (sc + i) * 16) = vb;
    }

    const int aoff = (w * 16 + g) * RB + tg * 4;

    int buf = 0;
#pragma unroll
    for (int s = 0; s < GSTEP; s++) {
        __syncthreads();

        uint4 pa[4], pb[4];
        if (s < GSTEP - 1) {
#pragma unroll
            for (int i = 0; i < 4; i++) {
                pa[i] = xs4[(m0 + sr) * 64 + (s + 1) * 8 + (sc + i)];
                pb[i] = Ts4[(n0 + sr) * 64 + (s + 1) * 8 + (sc + i)];
            }
        }

        const unsigned char* A = Asb[buf];
        const unsigned char* B = Bsb[buf];
#pragma unroll
        for (int kc = 0; kc < 4; kc++) {
            u32 a0 = *(const u32*)(A + aoff + kc * 32);
            u32 a1 = *(const u32*)(A + aoff + kc * 32 + 8 * RB);
            u32 a2 = *(const u32*)(A + aoff + kc * 32 + 16);
            u32 a3 = *(const u32*)(A + aoff + kc * 32 + 8 * RB + 16);
#pragma unroll
            for (int nc = 0; nc < 8; nc++) {
                const unsigned char* bp = B + (nc * 8 + g) * RB + tg * 4 + kc * 32;
                u32 b0 = *(const u32*)bp;
                u32 b1 = *(const u32*)(bp + 16);
                mma_bf16(d[nc][0], d[nc][1], d[nc][2], d[nc][3],
                         a0, a1, a2, a3, b0, b1);
            }
        }

        if (s < GSTEP - 1) {
            int b2 = buf ^ 1;
#pragma unroll
            for (int i = 0; i < 4; i++) {
                *(uint4*)(Asb[b2] + sr * RB + (sc + i) * 16) = pa[i];
                *(uint4*)(Bsb[b2] + sr * RB + (sc + i) * 16) = pb[i];
            }
        }
        buf ^= 1;
    }

    const int row0 = m0 + w * 16 + g;
#pragma unroll
    for (int nc = 0; nc < 8; nc++) {
        int col = n0 + nc * 8 + tg * 2;
        int o = col >> 4;
        int k = col & 15;
        g_Mb[(o * B_SZ + row0) * (KD / 2) + (k >> 1)]       = cvt2(d[nc][0], d[nc][1]);
        g_Mb[(o * B_SZ + row0 + 8) * (KD / 2) + (k >> 1)]   = cvt2(d[nc][2], d[nc][3]);
    }
}

// ---------------------------------------------------------------------------
// Kernel B: pairwise tiles + fused finalize (UNCHANGED from R13).
// ---------------------------------------------------------------------------
__device__ __forceinline__ float bterm(const uint4* __restrict__ s4,
                                       const u32* __restrict__ mjn, int i)
{
    uint4 va = s4[i * 2 + 0];
    uint4 vb = s4[i * 2 + 1];
    u32 d0 = habs2(hadd2b(va.x, mjn[0]));
    u32 d1 = habs2(hadd2b(va.y, mjn[1]));
    u32 d2 = habs2(hadd2b(va.z, mjn[2]));
    u32 d3 = habs2(hadd2b(va.w, mjn[3]));
    u32 d4 = habs2(hadd2b(vb.x, mjn[4]));
    u32 d5 = habs2(hadd2b(vb.y, mjn[5]));
    u32 d6 = habs2(hadd2b(vb.z, mjn[6]));
    u32 d7 = habs2(hadd2b(vb.w, mjn[7]));
    u32 t = hadd2b(hadd2b(hadd2b(d0, d1), hadd2b(d2, d3)),
                   hadd2b(hadd2b(d4, d5), hadd2b(d6, d7)));
    float lo = __uint_as_float(t << 16);
    float hi = __uint_as_float(t & 0xFFFF0000u);
    return __expf(-(lo + hi));
}

__global__ __launch_bounds__(128) void mbd_pairwise_kernel(
    const float* __restrict__ w, float* __restrict__ out)
{
    __shared__ u32 sJb[128 * 8];
    __shared__ u32 sIb[128 * 8];
    __shared__ int last;

    const int o   = blockIdx.x;
    const int jc  = blockIdx.y;
    const int q   = blockIdx.z;
    const int tid = threadIdx.x;
    const int j   = jc * 128 + tid;

    {
        const int offJ4 = (o * B_SZ + jc * 128) * 2;
        const int offI4 = (o * B_SZ + q  * 128) * 2;
#pragma unroll
        for (int t = 0; t < 2; t++) {
            int e = tid + t * 128;
            ((uint4*)sJb)[e] = ((const uint4*)g_Mb)[offJ4 + e];
            ((uint4*)sIb)[e] = ((const uint4*)g_Mb)[offI4 + e];
        }
    }
    __syncthreads();

    u32 mjn[8];
#pragma unroll
    for (int p = 0; p < 8; p++)
        mjn[p] = sJb[tid * 8 + p] ^ 0x80008000u;

    const uint4* s4 = (const uint4*)sIb;

    float S0 = 0.f, S1 = 0.f, S2 = 0.f, S3 = 0.f;
#pragma unroll 2
    for (int i = 0; i < 128; i += 4) {
        S0 += bterm(s4, mjn, i + 0);
        S1 += bterm(s4, mjn, i + 1);
        S2 += bterm(s4, mjn, i + 2);
        S3 += bterm(s4, mjn, i + 3);
    }
    float S = (S0 + S1) + (S2 + S3);

    atomicAdd(&g_S[o * B_SZ + j], S);

    __threadfence();
    __syncthreads();
    if (tid == 0)
        last = (atomicAdd(&g_cnt[o * 4 + jc], 1u) == 3u);
    __syncthreads();
    if (last) {
        __threadfence();
        float s = g_S[o * B_SZ + j];
        out[j * OUT_F + o] = w[j] * (s - 1.0f);
        if (tid == 0) g_cnt[o * 4 + jc] = 0u;
    }
}

// ---------------------------------------------------------------------------
extern "C" void kernel_launch(void* const* d_in, const int* in_sizes, int n_in,
                              void* d_out, int out_size)
{
    const float* x = (const float*)d_in[0];   // [512, 512]
    const float* w = (const float*)d_in[1];   // [1, 512]
    const float* T = (const float*)d_in[2];   // [512, 64, 16]
    float* out = (float*)d_out;               // [512, 64]

    (void)in_sizes; (void)n_in; (void)out_size;

    mbd_prep_kernel<<<dim3(16, 16), 256>>>(x, T);
    mbd_gemm_kernel<<<dim3(16, 8), 128>>>();
    mbd_pairwise_kernel<<<dim3(OUT_F, 4, 4), 128>>>(w, out);
}

// round 15
// speedup vs baseline: 1.1273x; 1.1273x over previous
#include <cuda_runtime.h>
#include <cuda_bf16.h>

// Problem constants
#define B_SZ   512
#define IN_F   512
#define OUT_F  64
#define KD     16
#define NF     (OUT_F * KD)   // 1024

typedef unsigned long long u64;
typedef unsigned int u32;

// Scratch: bf16 inputs (x row-major, T transposed), bf16 M [o][b][k/2], S, counters
__device__ u32 g_xb[B_SZ * IN_F / 2];          // x as bf16x2, [m][k]
__device__ u32 g_Tb[NF * IN_F / 2];            // T^T as bf16x2, [n][k]
__device__ u32 g_Mb[OUT_F * B_SZ * KD / 2];    // M as bf16x2, [o][b][k/2]
__device__ float g_S[OUT_F * B_SZ];
__device__ unsigned int g_cnt[OUT_F * 16];     // per (o, 32-row group), 16 contributors

// ---- packed helpers (sm_103a) ---------------------------------------------
__device__ __forceinline__ u32 hadd2b(u32 a, u32 b) {
    u32 r; asm("add.rn.bf16x2 %0, %1, %2;" : "=r"(r) : "r"(a), "r"(b)); return r;
}
__device__ __forceinline__ u32 habs2(u32 a) { return a & 0x7FFF7FFFu; }
__device__ __forceinline__ u32 cvt2(float lo, float hi) {
    u32 r; asm("cvt.rn.bf16x2.f32 %0, %1, %2;" : "=r"(r) : "f"(hi), "f"(lo)); return r;
}
__device__ __forceinline__ void mma_bf16(float& d0, float& d1, float& d2, float& d3,
                                         u32 a0, u32 a1, u32 a2, u32 a3,
                                         u32 b0, u32 b1) {
    asm volatile(
        "mma.sync.aligned.m16n8k16.row.col.f32.bf16.bf16.f32 "
        "{%0,%1,%2,%3}, {%4,%5,%6,%7}, {%8,%9}, {%0,%1,%2,%3};"
        : "+f"(d0), "+f"(d1), "+f"(d2), "+f"(d3)
        : "r"(a0), "r"(a1), "r"(a2), "r"(a3), "r"(b0), "r"(b1));
}

// ---------------------------------------------------------------------------
// Kernel P: prep (UNCHANGED from R14). Grid (16,16) x 256.
// ---------------------------------------------------------------------------
__global__ __launch_bounds__(256) void mbd_prep_kernel(
    const float* __restrict__ x, const float* __restrict__ T)
{
    __shared__ float sT[32][68];

    const int tid = threadIdx.x;
    const int bx  = blockIdx.x;
    const int by  = blockIdx.y;
    const int bid = by * 16 + bx;
    const int k0  = by * 32;
    const int n0  = bx * 64;

    {
        int e = bid * 256 + tid;
        float4 f = ((const float4*)x)[e];
        g_xb[e * 2 + 0] = cvt2(f.x, f.y);
        g_xb[e * 2 + 1] = cvt2(f.z, f.w);
    }
    if (tid < 128)
        g_S[bid * 128 + tid] = 0.0f;

    {
#pragma unroll
        for (int t = 0; t < 2; t++) {
            int idx = tid + t * 256;
            int r = idx >> 4;
            int c = idx & 15;
            float4 v = ((const float4*)T)[(k0 + r) * (NF / 4) + (n0 / 4) + c];
            *(float4*)&sT[r][c * 4] = v;
        }
    }
    __syncthreads();

    {
        int nn = tid >> 2;
        int kb = tid & 3;
#pragma unroll
        for (int i = 0; i < 4; i++) {
            int ki = kb * 4 + i;
            u32 v = cvt2(sT[ki * 2][nn], sT[ki * 2 + 1][nn]);
            g_Tb[(n0 + nn) * (IN_F / 2) + k0 / 2 + ki] = v;
        }
    }
}

// ---------------------------------------------------------------------------
// Kernel A: bf16 tensor-core GEMM (UNCHANGED from R13/R14).
// ---------------------------------------------------------------------------
#define GSTEP 8
#define RB 144

__global__ __launch_bounds__(128) void mbd_gemm_kernel(void)
{
    __shared__ unsigned char Asb[2][64 * RB];
    __shared__ unsigned char Bsb[2][64 * RB];

    const int tid = threadIdx.x;
    const int w   = tid >> 5;
    const int l   = tid & 31;
    const int g   = l >> 2;
    const int tg  = l & 3;
    const int nt  = blockIdx.x;
    const int mt  = blockIdx.y;
    const int m0  = mt * 64;
    const int n0  = nt * 64;

    const int sr = tid >> 1;
    const int sc = (tid & 1) * 4;
    const uint4* xs4 = (const uint4*)g_xb;
    const uint4* Ts4 = (const uint4*)g_Tb;

    float d[8][4];
#pragma unroll
    for (int nc = 0; nc < 8; nc++)
#pragma unroll
        for (int i = 0; i < 4; i++) d[nc][i] = 0.f;

#pragma unroll
    for (int i = 0; i < 4; i++) {
        uint4 va = xs4[(m0 + sr) * 64 + (sc + i)];
        uint4 vb = Ts4[(n0 + sr) * 64 + (sc + i)];
        *(uint4*)(Asb[0] + sr * RB + (sc + i) * 16) = va;
        *(uint4*)(Bsb[0] + sr * RB + (sc + i) * 16) = vb;
    }

    const int aoff = (w * 16 + g) * RB + tg * 4;

    int buf = 0;
#pragma unroll
    for (int s = 0; s < GSTEP; s++) {
        __syncthreads();

        uint4 pa[4], pb[4];
        if (s < GSTEP - 1) {
#pragma unroll
            for (int i = 0; i < 4; i++) {
                pa[i] = xs4[(m0 + sr) * 64 + (s + 1) * 8 + (sc + i)];
                pb[i] = Ts4[(n0 + sr) * 64 + (s + 1) * 8 + (sc + i)];
            }
        }

        const unsigned char* A = Asb[buf];
        const unsigned char* B = Bsb[buf];
#pragma unroll
        for (int kc = 0; kc < 4; kc++) {
            u32 a0 = *(const u32*)(A + aoff + kc * 32);
            u32 a1 = *(const u32*)(A + aoff + kc * 32 + 8 * RB);
            u32 a2 = *(const u32*)(A + aoff + kc * 32 + 16);
            u32 a3 = *(const u32*)(A + aoff + kc * 32 + 8 * RB + 16);
#pragma unroll
            for (int nc = 0; nc < 8; nc++) {
                const unsigned char* bp = B + (nc * 8 + g) * RB + tg * 4 + kc * 32;
                u32 b0 = *(const u32*)bp;
                u32 b1 = *(const u32*)(bp + 16);
                mma_bf16(d[nc][0], d[nc][1], d[nc][2], d[nc][3],
                         a0, a1, a2, a3, b0, b1);
            }
        }

        if (s < GSTEP - 1) {
            int b2 = buf ^ 1;
#pragma unroll
            for (int i = 0; i < 4; i++) {
                *(uint4*)(Asb[b2] + sr * RB + (sc + i) * 16) = pa[i];
                *(uint4*)(Bsb[b2] + sr * RB + (sc + i) * 16) = pb[i];
            }
        }
        buf ^= 1;
    }

    const int row0 = m0 + w * 16 + g;
#pragma unroll
    for (int nc = 0; nc < 8; nc++) {
        int col = n0 + nc * 8 + tg * 2;
        int o = col >> 4;
        int k = col & 15;
        g_Mb[(o * B_SZ + row0) * (KD / 2) + (k >> 1)]       = cvt2(d[nc][0], d[nc][1]);
        g_Mb[(o * B_SZ + row0 + 8) * (KD / 2) + (k >> 1)]   = cvt2(d[nc][2], d[nc][3]);
    }
}

// ---------------------------------------------------------------------------
// Kernel B: symmetric pairwise v2.
// Per o: 16 groups of 32 rows -> 120 off-diag + 16 diag group-pairs.
// grid (64, 34), 128 threads = 4 warps, warp = one group-pair.
// Off-diag warp: lane l owns j=ga*32+l; BROADCAST walk over i=gb*32+s.
// Each term feeds Sj (register) and SiPart (1 STS into padded transpose
// buffer); column sums after the loop give Si. Diag warp: plain loop.
// ---------------------------------------------------------------------------
__device__ __constant__ unsigned char PAIR_A[136] = {
 0,0,0,0,0,0,0,0,0,0,0,0,0,0,0,
 1,1,1,1,1,1,1,1,1,1,1,1,1,1,
 2,2,2,2,2,2,2,2,2,2,2,2,2,
 3,3,3,3,3,3,3,3,3,3,3,3,
 4,4,4,4,4,4,4,4,4,4,4,
 5,5,5,5,5,5,5,5,5,5,
 6,6,6,6,6,6,6,6,6,
 7,7,7,7,7,7,7,7,
 8,8,8,8,8,8,8,
 9,9,9,9,9,9,
 10,10,10,10,10,
 11,11,11,11,
 12,12,12,
 13,13,
 14,
 0,1,2,3,4,5,6,7,8,9,10,11,12,13,14,15};
__device__ __constant__ unsigned char PAIR_B[136] = {
 1,2,3,4,5,6,7,8,9,10,11,12,13,14,15,
 2,3,4,5,6,7,8,9,10,11,12,13,14,15,
 3,4,5,6,7,8,9,10,11,12,13,14,15,
 4,5,6,7,8,9,10,11,12,13,14,15,
 5,6,7,8,9,10,11,12,13,14,15,
 6,7,8,9,10,11,12,13,14,15,
 7,8,9,10,11,12,13,14,15,
 8,9,10,11,12,13,14,15,
 9,10,11,12,13,14,15,
 10,11,12,13,14,15,
 11,12,13,14,15,
 12,13,14,15,
 13,14,15,
 14,15,
 15,
 0,1,2,3,4,5,6,7,8,9,10,11,12,13,14,15};

__device__ __forceinline__ float bterm(const uint4* __restrict__ s4,
                                       const u32* __restrict__ mjn, int i)
{
    uint4 va = s4[i * 2 + 0];
    uint4 vb = s4[i * 2 + 1];
    u32 d0 = habs2(hadd2b(va.x, mjn[0]));
    u32 d1 = habs2(hadd2b(va.y, mjn[1]));
    u32 d2 = habs2(hadd2b(va.z, mjn[2]));
    u32 d3 = habs2(hadd2b(va.w, mjn[3]));
    u32 d4 = habs2(hadd2b(vb.x, mjn[4]));
    u32 d5 = habs2(hadd2b(vb.y, mjn[5]));
    u32 d6 = habs2(hadd2b(vb.z, mjn[6]));
    u32 d7 = habs2(hadd2b(vb.w, mjn[7]));
    u32 t = hadd2b(hadd2b(hadd2b(d0, d1), hadd2b(d2, d3)),
                   hadd2b(hadd2b(d4, d5), hadd2b(d6, d7)));
    float lo = __uint_as_float(t << 16);
    float hi = __uint_as_float(t & 0xFFFF0000u);
    return __expf(-(lo + hi));
}

__global__ __launch_bounds__(128) void mbd_pairwise_kernel(
    const float* __restrict__ w, float* __restrict__ out)
{
    __shared__ u32 sM[B_SZ * 8];               // whole o-slice, 16 KB
    __shared__ float sR[4][32 * 33];           // per-warp transpose, 16.5 KB

    const int o   = blockIdx.x;
    const int bp  = blockIdx.y;                // 0..33
    const int tid = threadIdx.x;
    const int wd  = tid >> 5;
    const int l   = tid & 31;
    const int pr  = bp * 4 + wd;               // pair 0..135
    const int ga  = PAIR_A[pr];
    const int gb  = PAIR_B[pr];
    const bool diag = (ga == gb);

    // Stage whole 512-row slice (1024 uint4, 8 per thread)
    {
        const uint4* src = ((const uint4*)g_Mb) + o * 1024;
        uint4* dst = (uint4*)sM;
#pragma unroll
        for (int t = 0; t < 8; t++)
            dst[tid + t * 128] = src[tid + t * 128];
    }
    __syncthreads();

    // Negated bf16x2 j-row (j = ga*32 + l)
    u32 mjn[8];
#pragma unroll
    for (int p = 0; p < 8; p++)
        mjn[p] = sM[(ga * 32 + l) * 8 + p] ^ 0x80008000u;

    const uint4* s4 = (const uint4*)sM + gb * 64;   // i-group base (2 uint4/row)

    if (diag) {
        float S0 = 0.f, S1 = 0.f, S2 = 0.f, S3 = 0.f;
#pragma unroll
        for (int s = 0; s < 32; s += 4) {
            S0 += bterm(s4, mjn, s + 0);
            S1 += bterm(s4, mjn, s + 1);
            S2 += bterm(s4, mjn, s + 2);
            S3 += bterm(s4, mjn, s + 3);
        }
        atomicAdd(&g_S[o * B_SZ + ga * 32 + l], (S0 + S1) + (S2 + S3));
    } else {
        float* myR = sR[wd];
        float Sj = 0.f;
#pragma unroll
        for (int s = 0; s < 32; s++) {
            float term = bterm(s4, mjn, s);
            Sj += term;
            myR[l * 33 + s] = term;            // banks (l+s)%32: conflict-free
        }
        __syncwarp();
        // Column sum: Si for i = gb*32 + l  (reads banks (m+l)%32: c-free)
        float A0 = 0.f, A1 = 0.f, A2 = 0.f, A3 = 0.f;
#pragma unroll
        for (int m = 0; m < 32; m += 4) {
            A0 += myR[(m + 0) * 33 + l];
            A1 += myR[(m + 1) * 33 + l];
            A2 += myR[(m + 2) * 33 + l];
            A3 += myR[(m + 3) * 33 + l];
        }
        float Si = (A0 + A1) + (A2 + A3);
        atomicAdd(&g_S[o * B_SZ + ga * 32 + l], Sj);
        atomicAdd(&g_S[o * B_SZ + gb * 32 + l], Si);
    }

    // Finalize: each group has exactly 16 contributing warps
    __threadfence();
    u32 doneA = 0, doneB = 0;
    if (l == 0) {
        doneA = (atomicAdd(&g_cnt[o * 16 + ga], 1u) == 15u);
        if (!diag)
            doneB = (atomicAdd(&g_cnt[o * 16 + gb], 1u) == 15u);
    }
    doneA = __shfl_sync(0xffffffffu, doneA, 0);
    doneB = __shfl_sync(0xffffffffu, doneB, 0);
    if (doneA) {
        __threadfence();                       // acquire: see peers' adds
        int jj = ga * 32 + l;
        out[jj * OUT_F + o] = w[jj] * (g_S[o * B_SZ + jj] - 1.0f);
        if (l == 0) g_cnt[o * 16 + ga] = 0u;   // reset for graph replay
    }
    if (doneB) {
        __threadfence();
        int jj = gb * 32 + l;
        out[jj * OUT_F + o] = w[jj] * (g_S[o * B_SZ + jj] - 1.0f);
        if (l == 0) g_cnt[o * 16 + gb] = 0u;
    }
}

// ---------------------------------------------------------------------------
extern "C" void kernel_launch(void* const* d_in, const int* in_sizes, int n_in,
                              void* d_out, int out_size)
{
    const float* x = (const float*)d_in[0];   // [512, 512]
    const float* w = (const float*)d_in[1];   // [1, 512]
    const float* T = (const float*)d_in[2];   // [512, 64, 16]
    float* out = (float*)d_out;               // [512, 64]

    (void)in_sizes; (void)n_in; (void)out_size;

    mbd_prep_kernel<<<dim3(16, 16), 256>>>(x, T);
    mbd_gemm_kernel<<<dim3(16, 8), 128>>>();
    mbd_pairwise_kernel<<<dim3(OUT_F, 34), 128>>>(w, out);
}

// round 16
// speedup vs baseline: 1.1746x; 1.0420x over previous
#include <cuda_runtime.h>
#include <cuda_bf16.h>

// Problem constants
#define B_SZ   512
#define IN_F   512
#define OUT_F  64
#define KD     16
#define NF     (OUT_F * KD)   // 1024

typedef unsigned long long u64;
typedef unsigned int u32;

// Scratch: bf16 inputs (x row-major, T transposed), bf16 M [o][b][k/2], S, counters
__device__ u32 g_xb[B_SZ * IN_F / 2];          // x as bf16x2, [m][k]
__device__ u32 g_Tb[NF * IN_F / 2];            // T^T as bf16x2, [n][k]
__device__ u32 g_Mb[OUT_F * B_SZ * KD / 2];    // M as bf16x2, [o][b][k/2]
__device__ float g_S[OUT_F * B_SZ];
__device__ unsigned int g_cnt[OUT_F * 16];     // per (o, 32-row group), 16 contributors

// ---- packed helpers (sm_103a) ---------------------------------------------
__device__ __forceinline__ u32 hadd2b(u32 a, u32 b) {
    u32 r; asm("add.rn.bf16x2 %0, %1, %2;" : "=r"(r) : "r"(a), "r"(b)); return r;
}
__device__ __forceinline__ u32 habs2(u32 a) { return a & 0x7FFF7FFFu; }
__device__ __forceinline__ u32 cvt2(float lo, float hi) {
    u32 r; asm("cvt.rn.bf16x2.f32 %0, %1, %2;" : "=r"(r) : "f"(hi), "f"(lo)); return r;
}
__device__ __forceinline__ void mma_bf16(float& d0, float& d1, float& d2, float& d3,
                                         u32 a0, u32 a1, u32 a2, u32 a3,
                                         u32 b0, u32 b1) {
    asm volatile(
        "mma.sync.aligned.m16n8k16.row.col.f32.bf16.bf16.f32 "
        "{%0,%1,%2,%3}, {%4,%5,%6,%7}, {%8,%9}, {%0,%1,%2,%3};"
        : "+f"(d0), "+f"(d1), "+f"(d2), "+f"(d3)
        : "r"(a0), "r"(a1), "r"(a2), "r"(a3), "r"(b0), "r"(b1));
}

// ---------------------------------------------------------------------------
// Kernel P: prep. Grid (16 n-tiles, 32 k-tiles) = 512 blocks x 256 threads.
// One global load per thread everywhere -> short chains, high parallelism.
// ---------------------------------------------------------------------------
__global__ __launch_bounds__(256) void mbd_prep_kernel(
    const float* __restrict__ x, const float* __restrict__ T)
{
    __shared__ float sT[16][68];               // padded rows

    const int tid = threadIdx.x;
    const int bx  = blockIdx.x;                // n tile (64 wide)
    const int by  = blockIdx.y;                // k tile (16 tall)
    const int bid = by * 16 + bx;              // 0..511
    const int k0  = by * 16;
    const int n0  = bx * 64;

    // x conversion: 65536 float4 -> 128 per block (tid < 128)
    if (tid < 128) {
        int e = bid * 128 + tid;
        float4 f = ((const float4*)x)[e];
        g_xb[e * 2 + 0] = cvt2(f.x, f.y);
        g_xb[e * 2 + 1] = cvt2(f.z, f.w);
    } else {
        // g_S zeroing: 32768 floats -> 64 per block (tid 128..191)
        if (tid < 192)
            g_S[bid * 64 + (tid - 128)] = 0.0f;
    }

    // Load T tile (16 k-rows x 64 n-cols): 256 float4, 1 per thread
    {
        int r = tid >> 4;                      // 0..15
        int c = tid & 15;                      // float4 col
        float4 v = ((const float4*)T)[(k0 + r) * (NF / 4) + (n0 / 4) + c];
        *(float4*)&sT[r][c * 4] = v;
    }
    __syncthreads();

    // Write transposed bf16x2: g_Tb[n][k/2], 512 u32, 2 per thread
    {
        int nn = tid >> 2;                     // 0..63
        int kb = tid & 3;
#pragma unroll
        for (int i = 0; i < 2; i++) {
            int ki = kb * 2 + i;               // u32 index within tile, 0..7
            u32 v = cvt2(sT[ki * 2][nn], sT[ki * 2 + 1][nn]);
            g_Tb[(n0 + nn) * (IN_F / 2) + k0 / 2 + ki] = v;
        }
    }
}

// ---------------------------------------------------------------------------
// Kernel A: bf16 tensor-core GEMM (UNCHANGED from R13-R15).
// ---------------------------------------------------------------------------
#define GSTEP 8
#define RB 144

__global__ __launch_bounds__(128) void mbd_gemm_kernel(void)
{
    __shared__ unsigned char Asb[2][64 * RB];
    __shared__ unsigned char Bsb[2][64 * RB];

    const int tid = threadIdx.x;
    const int w   = tid >> 5;
    const int l   = tid & 31;
    const int g   = l >> 2;
    const int tg  = l & 3;
    const int nt  = blockIdx.x;
    const int mt  = blockIdx.y;
    const int m0  = mt * 64;
    const int n0  = nt * 64;

    const int sr = tid >> 1;
    const int sc = (tid & 1) * 4;
    const uint4* xs4 = (const uint4*)g_xb;
    const uint4* Ts4 = (const uint4*)g_Tb;

    float d[8][4];
#pragma unroll
    for (int nc = 0; nc < 8; nc++)
#pragma unroll
        for (int i = 0; i < 4; i++) d[nc][i] = 0.f;

#pragma unroll
    for (int i = 0; i < 4; i++) {
        uint4 va = xs4[(m0 + sr) * 64 + (sc + i)];
        uint4 vb = Ts4[(n0 + sr) * 64 + (sc + i)];
        *(uint4*)(Asb[0] + sr * RB + (sc + i) * 16) = va;
        *(uint4*)(Bsb[0] + sr * RB + (sc + i) * 16) = vb;
    }

    const int aoff = (w * 16 + g) * RB + tg * 4;

    int buf = 0;
#pragma unroll
    for (int s = 0; s < GSTEP; s++) {
        __syncthreads();

        uint4 pa[4], pb[4];
        if (s < GSTEP - 1) {
#pragma unroll
            for (int i = 0; i < 4; i++) {
                pa[i] = xs4[(m0 + sr) * 64 + (s + 1) * 8 + (sc + i)];
                pb[i] = Ts4[(n0 + sr) * 64 + (s + 1) * 8 + (sc + i)];
            }
        }

        const unsigned char* A = Asb[buf];
        const unsigned char* B = Bsb[buf];
#pragma unroll
        for (int kc = 0; kc < 4; kc++) {
            u32 a0 = *(const u32*)(A + aoff + kc * 32);
            u32 a1 = *(const u32*)(A + aoff + kc * 32 + 8 * RB);
            u32 a2 = *(const u32*)(A + aoff + kc * 32 + 16);
            u32 a3 = *(const u32*)(A + aoff + kc * 32 + 8 * RB + 16);
#pragma unroll
            for (int nc = 0; nc < 8; nc++) {
                const unsigned char* bp = B + (nc * 8 + g) * RB + tg * 4 + kc * 32;
                u32 b0 = *(const u32*)bp;
                u32 b1 = *(const u32*)(bp + 16);
                mma_bf16(d[nc][0], d[nc][1], d[nc][2], d[nc][3],
                         a0, a1, a2, a3, b0, b1);
            }
        }

        if (s < GSTEP - 1) {
            int b2 = buf ^ 1;
#pragma unroll
            for (int i = 0; i < 4; i++) {
                *(uint4*)(Asb[b2] + sr * RB + (sc + i) * 16) = pa[i];
                *(uint4*)(Bsb[b2] + sr * RB + (sc + i) * 16) = pb[i];
            }
        }
        buf ^= 1;
    }

    const int row0 = m0 + w * 16 + g;
#pragma unroll
    for (int nc = 0; nc < 8; nc++) {
        int col = n0 + nc * 8 + tg * 2;
        int o = col >> 4;
        int k = col & 15;
        g_Mb[(o * B_SZ + row0) * (KD / 2) + (k >> 1)]       = cvt2(d[nc][0], d[nc][1]);
        g_Mb[(o * B_SZ + row0 + 8) * (KD / 2) + (k >> 1)]   = cvt2(d[nc][2], d[nc][3]);
    }
}

// ---------------------------------------------------------------------------
// Kernel B: symmetric pairwise v2.1.
// CHANGES vs R15: 256 threads (8 warps = 8 pairs/block, grid (64,17)) so the
// 16 KB slice staging is shared by 8 pairs (half the L2 traffic); transpose
// buffer uses an additive swizzle instead of padding (fits 48 KB exactly).
// ---------------------------------------------------------------------------
__device__ __constant__ unsigned char PAIR_A[136] = {
 0,0,0,0,0,0,0,0,0,0,0,0,0,0,0,
 1,1,1,1,1,1,1,1,1,1,1,1,1,1,
 2,2,2,2,2,2,2,2,2,2,2,2,2,
 3,3,3,3,3,3,3,3,3,3,3,3,
 4,4,4,4,4,4,4,4,4,4,4,
 5,5,5,5,5,5,5,5,5,5,
 6,6,6,6,6,6,6,6,6,
 7,7,7,7,7,7,7,7,
 8,8,8,8,8,8,8,
 9,9,9,9,9,9,
 10,10,10,10,10,
 11,11,11,11,
 12,12,12,
 13,13,
 14,
 0,1,2,3,4,5,6,7,8,9,10,11,12,13,14,15};
__device__ __constant__ unsigned char PAIR_B[136] = {
 1,2,3,4,5,6,7,8,9,10,11,12,13,14,15,
 2,3,4,5,6,7,8,9,10,11,12,13,14,15,
 3,4,5,6,7,8,9,10,11,12,13,14,15,
 4,5,6,7,8,9,10,11,12,13,14,15,
 5,6,7,8,9,10,11,12,13,14,15,
 6,7,8,9,10,11,12,13,14,15,
 7,8,9,10,11,12,13,14,15,
 8,9,10,11,12,13,14,15,
 9,10,11,12,13,14,15,
 10,11,12,13,14,15,
 11,12,13,14,15,
 12,13,14,15,
 13,14,15,
 14,15,
 15,
 0,1,2,3,4,5,6,7,8,9,10,11,12,13,14,15};

__device__ __forceinline__ float bterm(const uint4* __restrict__ s4,
                                       const u32* __restrict__ mjn, int i)
{
    uint4 va = s4[i * 2 + 0];
    uint4 vb = s4[i * 2 + 1];
    u32 d0 = habs2(hadd2b(va.x, mjn[0]));
    u32 d1 = habs2(hadd2b(va.y, mjn[1]));
    u32 d2 = habs2(hadd2b(va.z, mjn[2]));
    u32 d3 = habs2(hadd2b(va.w, mjn[3]));
    u32 d4 = habs2(hadd2b(vb.x, mjn[4]));
    u32 d5 = habs2(hadd2b(vb.y, mjn[5]));
    u32 d6 = habs2(hadd2b(vb.z, mjn[6]));
    u32 d7 = habs2(hadd2b(vb.w, mjn[7]));
    u32 t = hadd2b(hadd2b(hadd2b(d0, d1), hadd2b(d2, d3)),
                   hadd2b(hadd2b(d4, d5), hadd2b(d6, d7)));
    float lo = __uint_as_float(t << 16);
    float hi = __uint_as_float(t & 0xFFFF0000u);
    return __expf(-(lo + hi));
}

__global__ __launch_bounds__(256) void mbd_pairwise_kernel(
    const float* __restrict__ w, float* __restrict__ out)
{
    __shared__ u32 sM[B_SZ * 8];               // whole o-slice, 16 KB
    __shared__ float sR[8][32 * 32];           // per-warp swizzled, 32 KB

    const int o   = blockIdx.x;
    const int bp  = blockIdx.y;                // 0..16
    const int tid = threadIdx.x;
    const int wd  = tid >> 5;
    const int l   = tid & 31;
    const int pr  = bp * 8 + wd;               // pair 0..135
    const int ga  = PAIR_A[pr];
    const int gb  = PAIR_B[pr];
    const bool diag = (ga == gb);

    // Stage whole 512-row slice (1024 uint4, 4 per thread)
    {
        const uint4* src = ((const uint4*)g_Mb) + o * 1024;
        uint4* dst = (uint4*)sM;
#pragma unroll
        for (int t = 0; t < 4; t++)
            dst[tid + t * 256] = src[tid + t * 256];
    }
    __syncthreads();

    // Negated bf16x2 j-row (j = ga*32 + l)
    u32 mjn[8];
#pragma unroll
    for (int p = 0; p < 8; p++)
        mjn[p] = sM[(ga * 32 + l) * 8 + p] ^ 0x80008000u;

    const uint4* s4 = (const uint4*)sM + gb * 64;   // i-group base (2 uint4/row)

    if (diag) {
        float S0 = 0.f, S1 = 0.f, S2 = 0.f, S3 = 0.f;
#pragma unroll
        for (int s = 0; s < 32; s += 4) {
            S0 += bterm(s4, mjn, s + 0);
            S1 += bterm(s4, mjn, s + 1);
            S2 += bterm(s4, mjn, s + 2);
            S3 += bterm(s4, mjn, s + 3);
        }
        atomicAdd(&g_S[o * B_SZ + ga * 32 + l], (S0 + S1) + (S2 + S3));
    } else {
        float* myR = sR[wd];
        float Sj = 0.f;
        // store swizzle: row l, step s -> l*32 + (s+l)%32  (banks (s+l)%32)
#pragma unroll
        for (int s = 0; s < 32; s++) {
            float term = bterm(s4, mjn, s);
            Sj += term;
            myR[l * 32 + ((s + l) & 31)] = term;
        }
        __syncwarp();
        // column read: element (m, l) at m*32 + (l+m)%32  (banks (l+m)%32)
        float A0 = 0.f, A1 = 0.f, A2 = 0.f, A3 = 0.f;
#pragma unroll
        for (int m = 0; m < 32; m += 4) {
            A0 += myR[(m + 0) * 32 + ((l + m + 0) & 31)];
            A1 += myR[(m + 1) * 32 + ((l + m + 1) & 31)];
            A2 += myR[(m + 2) * 32 + ((l + m + 2) & 31)];
            A3 += myR[(m + 3) * 32 + ((l + m + 3) & 31)];
        }
        float Si = (A0 + A1) + (A2 + A3);
        atomicAdd(&g_S[o * B_SZ + ga * 32 + l], Sj);
        atomicAdd(&g_S[o * B_SZ + gb * 32 + l], Si);
    }

    // Finalize: each group has exactly 16 contributing warps
    __threadfence();
    u32 doneA = 0, doneB = 0;
    if (l == 0) {
        doneA = (atomicAdd(&g_cnt[o * 16 + ga], 1u) == 15u);
        if (!diag)
            doneB = (atomicAdd(&g_cnt[o * 16 + gb], 1u) == 15u);
    }
    doneA = __shfl_sync(0xffffffffu, doneA, 0);
    doneB = __shfl_sync(0xffffffffu, doneB, 0);
    if (doneA) {
        __threadfence();                       // acquire: see peers' adds
        int jj = ga * 32 + l;
        out[jj * OUT_F + o] = w[jj] * (g_S[o * B_SZ + jj] - 1.0f);
        if (l == 0) g_cnt[o * 16 + ga] = 0u;   // reset for graph replay
    }
    if (doneB) {
        __threadfence();
        int jj = gb * 32 + l;
        out[jj * OUT_F + o] = w[jj] * (g_S[o * B_SZ + jj] - 1.0f);
        if (l == 0) g_cnt[o * 16 + gb] = 0u;
    }
}

// ---------------------------------------------------------------------------
extern "C" void kernel_launch(void* const* d_in, const int* in_sizes, int n_in,
                              void* d_out, int out_size)
{
    const float* x = (const float*)d_in[0];   // [512, 512]
    const float* w = (const float*)d_in[1];   // [1, 512]
    const float* T = (const float*)d_in[2];   // [512, 64, 16]
    float* out = (float*)d_out;               // [512, 64]

    (void)in_sizes; (void)n_in; (void)out_size;

    mbd_prep_kernel<<<dim3(16, 32), 256>>>(x, T);
    mbd_gemm_kernel<<<dim3(16, 8), 128>>>();
    mbd_pairwise_kernel<<<dim3(OUT_F, 17), 256>>>(w, out);
}